// round 14
// baseline (speedup 1.0000x reference)
#include <cuda_runtime.h>
#include <cuda_fp16.h>
#include <cstdint>
#include <math.h>

// QKVAttention v13: identical to v12 except __launch_bounds__(128, 3) ->
// ptxas targets <=170 regs so 3 CTAs/SM (12 warps, 3 per SMSP) can hide the
// MMA/MUFU/LDS latencies that serialize at 2 warps/SMSP. All-fp16 operands
// (fp32 accum), fragment-order prepacked K/V (every B-fragment = 1 LDS.128),
// register-resident P, double-buffered cp.async, two barriers/tile.

#define CH 64
#define TT 2048
#define SSEQ 2048
#define BM 128
#define BN 64
#define NTILES (SSEQ / BN)
#define NTHREADS 128
#define MAXELEM (4 * 512 * 2048)

#define PADQ 136    // uint32 units, Q staging 32 rows
#define PADO 132

// fragment-order buffers: K tile = 2048 words (16 blocks x 128), V same
#define KBUF 2048
#define OFF_V (2 * KBUF)     // 4096
#define VBUF 2048
#define SMEM_WORDS 8448      // max(buffers 8192, Osm 64*132=8448)
#define SMEM_BYTES (SMEM_WORDS * 4)

__device__ uint32_t g_Qp[MAXELEM / 2];   // [bh][32 cp][2048 t] fp16x2
__device__ uint32_t g_Kp[MAXELEM / 2];   // [bh][32 tiles][16 blk][32 lane][4 w]
__device__ uint32_t g_Vp[MAXELEM / 2];   // [bh][32 tiles][16 blk][32 lane][4 w]

__device__ __forceinline__ uint32_t smem_u32(const void* p) {
    uint32_t a;
    asm("{ .reg .u64 t; cvta.to.shared.u64 t, %1; cvt.u32.u64 %0, t; }" : "=r"(a) : "l"(p));
    return a;
}
__device__ __forceinline__ void cpa16(uint32_t dst, const void* src) {
    asm volatile("cp.async.cg.shared.global [%0], [%1], 16;" :: "r"(dst), "l"(src));
}
#define CP_COMMIT() asm volatile("cp.async.commit_group;" ::: "memory")
#define CP_WAIT0()  asm volatile("cp.async.wait_group 0;" ::: "memory")
#define CP_WAIT1()  asm volatile("cp.async.wait_group 1;" ::: "memory")

__device__ __forceinline__ uint32_t packh2(float lo, float hi) {
    __half2 h = __floats2half2_rn(lo, hi);
    return *reinterpret_cast<uint32_t*>(&h);
}

__device__ __forceinline__ void mma_f16(float* d, const uint32_t* a, uint32_t b0, uint32_t b1) {
    asm volatile(
        "mma.sync.aligned.m16n8k16.row.col.f32.f16.f16.f32 "
        "{%0,%1,%2,%3}, {%4,%5,%6,%7}, {%8,%9}, {%0,%1,%2,%3};"
        : "+f"(d[0]), "+f"(d[1]), "+f"(d[2]), "+f"(d[3])
        : "r"(a[0]), "r"(a[1]), "r"(a[2]), "r"(a[3]), "r"(b0), "r"(b1));
}

// ---- pre-pass: Q -> fp16x2 [bh][cp][t] (scaled); K,V -> fragment-order ----
__global__ void __launch_bounds__(256)
prep_kernel(const float* __restrict__ q, const float* __restrict__ k,
            const float* __restrict__ v, int nelem) {
    const float qsc = 1.4426950408889634f / 64.0f;  // log2e * (1/64)
    int i = blockIdx.x * blockDim.x + threadIdx.x;
    int ob = i * 4;                       // uint32 output index (16B aligned)
    if (ob >= nelem / 2) return;

    // --- Q: pack channel pairs, [bh][cp][t] ---
    {
        int t4 = ob & (TT - 1);
        int cp = (ob >> 11) & 31;
        int bh = ob >> 16;
        const float* q0 = q + ((size_t)(bh * 64 + 2 * cp)) * TT + t4;
        const float* q1 = q0 + TT;
        float4 qa = *(const float4*)q0;
        float4 qb = *(const float4*)q1;
        uint32_t* oq = g_Qp + ob;
        oq[0] = packh2(qa.x * qsc, qb.x * qsc);
        oq[1] = packh2(qa.y * qsc, qb.y * qsc);
        oq[2] = packh2(qa.z * qsc, qb.z * qsc);
        oq[3] = packh2(qa.w * qsc, qb.w * qsc);
    }

    // shared decomposition for fragment-order outputs
    int lane = (ob >> 2) & 31;
    int blk  = (ob >> 7) & 15;
    int tau  = (ob >> 11) & 31;
    int bh   = ob >> 16;
    int tg = lane & 3, g = lane >> 2;

    // --- K fragment-order: blk = nc*8 + kk*2 + nbh ---
    {
        int nbh = blk & 1, kk = (blk >> 1) & 3, nc = blk >> 3;
        uint32_t* ok = g_Kp + ob;
        #pragma unroll
        for (int w = 0; w < 4; w++) {
            int cp = kk * 8 + tg + (w & 1) * 4;
            int s = tau * 64 + nc * 32 + nbh * 16 + (w >> 1) * 8 + g;
            const float* ksrc = k + ((size_t)(bh * 64 + 2 * cp)) * SSEQ + s;
            ok[w] = packh2(ksrc[0], ksrc[SSEQ]);
        }
    }

    // --- V fragment-order: blk = nc*8 + nb ---
    {
        int nb = blk & 7, nc = blk >> 3;
        int c = nb * 8 + g;
        uint32_t* ov = g_Vp + ob;
        #pragma unroll
        for (int w = 0; w < 4; w++) {
            int sp = tau * 32 + nc * 16 + (w >> 1) * 8 + (w & 1) * 4 + tg;
            const float* vsrc = v + ((size_t)(bh * 64 + c)) * SSEQ + 2 * sp;
            ov[w] = packh2(vsrc[0], vsrc[1]);
        }
    }
}

__global__ void __launch_bounds__(NTHREADS, 3)
fattn_v13(float* __restrict__ out) {
    extern __shared__ float sm[];
    const uint32_t smu = smem_u32(sm);
    uint32_t* smw = reinterpret_cast<uint32_t*>(sm);

    const int tid  = threadIdx.x;
    const int lane = tid & 31;
    const int g    = lane >> 2;
    const int tg   = lane & 3;
    const int bh   = blockIdx.y;
    const int t0   = blockIdx.x * BM;
    const int mw   = (tid >> 5) * 32;    // warp's 32-row slab

    const uint32_t* qp = g_Qp + (size_t)bh * 32 * TT;
    const uint32_t* kp = g_Kp + (size_t)bh * 32 * TT;   // 32 tiles x 2048 words
    const uint32_t* vp = g_Vp + (size_t)bh * 32 * TT;

    // ---- stage packed Q [cp][t], extract fp16 A-frags ----
    #pragma unroll
    for (int j = 0; j < 8; j++) {
        int idx = tid + j * NTHREADS;            // 1024 chunks = 32 rows x 32
        int cp = idx >> 5, t4 = (idx & 31) << 2;
        uint4 r = *(const uint4*)(qp + (size_t)cp * TT + t0 + t4);
        *(uint4*)(smw + cp * PADQ + t4) = r;
    }
    __syncthreads();

    uint32_t Aq[2][4][4];
    #pragma unroll
    for (int mb = 0; mb < 2; mb++) {
        int r = mw + mb * 16;
        #pragma unroll
        for (int kk = 0; kk < 4; kk++) {
            Aq[mb][kk][0] = smw[(kk * 8 + tg)     * PADQ + r + g];
            Aq[mb][kk][1] = smw[(kk * 8 + tg)     * PADQ + r + g + 8];
            Aq[mb][kk][2] = smw[(kk * 8 + tg + 4) * PADQ + r + g];
            Aq[mb][kk][3] = smw[(kk * 8 + tg + 4) * PADQ + r + g + 8];
        }
    }
    __syncthreads();   // Q staging dead; K/V buffers may now be written

    float O[2][8][4];
    #pragma unroll
    for (int mb = 0; mb < 2; mb++)
        #pragma unroll
        for (int nb = 0; nb < 8; nb++)
            O[mb][nb][0] = O[mb][nb][1] = O[mb][nb][2] = O[mb][nb][3] = 0.f;
    float srow[2][2] = {{0.f, 0.f}, {0.f, 0.f}};

    // ---- prologue: async-load tile 0 (linear 16B chunks) ----
    {
        #pragma unroll
        for (int j = 0; j < 4; j++) {
            int idx = tid + j * NTHREADS;        // 512 chunks each
            cpa16(smu + (uint32_t)(idx * 16), kp + idx * 4);
            cpa16(smu + (uint32_t)((OFF_V + idx * 4) * 4), vp + idx * 4);
        }
        CP_COMMIT();
    }

    #pragma unroll 1
    for (int tile = 0; tile < NTILES; tile++) {
        const int nbuf = tile & 1;
        if (tile + 1 < NTILES) {
            const int obuf = (tile + 1) & 1;
            const uint32_t* kt = kp + (size_t)(tile + 1) * 2048;
            const uint32_t* vt = vp + (size_t)(tile + 1) * 2048;
            #pragma unroll
            for (int j = 0; j < 4; j++) {
                int idx = tid + j * NTHREADS;
                cpa16(smu + (uint32_t)((obuf * KBUF + idx * 4) * 4), kt + idx * 4);
                cpa16(smu + (uint32_t)((OFF_V + obuf * VBUF + idx * 4) * 4), vt + idx * 4);
            }
            CP_COMMIT();
            CP_WAIT1();
        } else {
            CP_WAIT0();
        }
        __syncthreads();   // tile's K/V visible; prev readers done (end barrier)

        const uint32_t* Ks = smw + nbuf * KBUF;
        const uint32_t* Vs = smw + OFF_V + nbuf * VBUF;

        // ---- per n32-chunk: GEMM1(f16) -> exp2 -> pack fp16 -> GEMM2(f16) ----
        #pragma unroll
        for (int nc = 0; nc < 2; nc++) {
            float S[4][2][4];
            #pragma unroll
            for (int nbi = 0; nbi < 4; nbi++)
                #pragma unroll
                for (int mb = 0; mb < 2; mb++)
                    S[nbi][mb][0] = S[nbi][mb][1] = S[nbi][mb][2] = S[nbi][mb][3] = 0.f;

            #pragma unroll
            for (int kk = 0; kk < 4; kk++) {
                #pragma unroll
                for (int nbh = 0; nbh < 2; nbh++) {
                    uint4 F = *(const uint4*)(Ks + nc * 1024 + (kk * 2 + nbh) * 128 + lane * 4);
                    mma_f16(S[2 * nbh + 0][0], Aq[0][kk], F.x, F.y);
                    mma_f16(S[2 * nbh + 0][1], Aq[1][kk], F.x, F.y);
                    mma_f16(S[2 * nbh + 1][0], Aq[0][kk], F.z, F.w);
                    mma_f16(S[2 * nbh + 1][1], Aq[1][kk], F.z, F.w);
                }
            }

            // exp2 + pack to fp16x2 A-frags; j-th k16 chunk = nbi pair (2j,2j+1)
            uint32_t Ap[2][2][4];   // [j][mb][4]
            #pragma unroll
            for (int j = 0; j < 2; j++) {
                #pragma unroll
                for (int mb = 0; mb < 2; mb++) {
                    float e0 = exp2f(S[2 * j][mb][0]),     e1 = exp2f(S[2 * j][mb][1]);
                    float e2 = exp2f(S[2 * j][mb][2]),     e3 = exp2f(S[2 * j][mb][3]);
                    float f0 = exp2f(S[2 * j + 1][mb][0]), f1 = exp2f(S[2 * j + 1][mb][1]);
                    float f2 = exp2f(S[2 * j + 1][mb][2]), f3 = exp2f(S[2 * j + 1][mb][3]);
                    srow[mb][0] += (e0 + e1) + (f0 + f1);
                    srow[mb][1] += (e2 + e3) + (f2 + f3);
                    Ap[j][mb][0] = packh2(e0, e1);
                    Ap[j][mb][1] = packh2(e2, e3);
                    Ap[j][mb][2] = packh2(f0, f1);
                    Ap[j][mb][3] = packh2(f2, f3);
                }
            }

            // GEMM2 partial: F.x/F.y -> j=0 (s-pairs nc*16+0..7), F.z/F.w -> j=1
            #pragma unroll
            for (int nb = 0; nb < 8; nb++) {
                uint4 F = *(const uint4*)(Vs + nc * 1024 + nb * 128 + lane * 4);
                mma_f16(O[0][nb], Ap[0][0], F.x, F.y);
                mma_f16(O[1][nb], Ap[0][1], F.x, F.y);
                mma_f16(O[0][nb], Ap[1][0], F.z, F.w);
                mma_f16(O[1][nb], Ap[1][1], F.z, F.w);
            }
        }
        __syncthreads();   // all warps done reading Ks/Vs before next prefetch
    }

    // ---- row-sum reduce over tg ----
    #pragma unroll
    for (int mb = 0; mb < 2; mb++)
        #pragma unroll
        for (int rr = 0; rr < 2; rr++) {
            float s = srow[mb][rr];
            s += __shfl_xor_sync(0xffffffffu, s, 1);
            s += __shfl_xor_sync(0xffffffffu, s, 2);
            srow[mb][rr] = s;
        }

    // ---- epilogue: normalize + transpose via smem (overlay), coalesced store ----
    float* Osm = sm;
    #pragma unroll
    for (int mb = 0; mb < 2; mb++) {
        float i0 = 1.0f / srow[mb][0];
        float i1 = 1.0f / srow[mb][1];
        int r = mw + mb * 16;
        #pragma unroll
        for (int nb = 0; nb < 8; nb++) {
            int col = nb * 8 + 2 * tg;
            Osm[(col + 0) * PADO + r + g]     = O[mb][nb][0] * i0;
            Osm[(col + 1) * PADO + r + g]     = O[mb][nb][1] * i0;
            Osm[(col + 0) * PADO + r + g + 8] = O[mb][nb][2] * i1;
            Osm[(col + 1) * PADO + r + g + 8] = O[mb][nb][3] * i1;
        }
    }
    __syncthreads();

    float* ob = out + (size_t)bh * CH * TT + t0;
    #pragma unroll
    for (int j = 0; j < 16; j++) {
        int idx = tid + j * NTHREADS;
        int c = idx >> 5, t4 = (idx & 31) << 2;
        *(float4*)(ob + (size_t)c * TT + t4) = *(const float4*)(Osm + c * PADO + t4);
    }
}

extern "C" void kernel_launch(void* const* d_in, const int* in_sizes, int n_in,
                              void* d_out, int out_size) {
    const float* q = (const float*)d_in[0];
    const float* k = (const float*)d_in[1];
    const float* v = (const float*)d_in[2];
    float* out = (float*)d_out;

    int nelem = in_sizes[0];
    int nbh = nelem / (CH * TT);   // 32

    prep_kernel<<<(nelem / 8 + 255) / 256, 256>>>(q, k, v, nelem);

    cudaFuncSetAttribute(fattn_v13,
                         cudaFuncAttributeMaxDynamicSharedMemorySize, SMEM_BYTES);
    dim3 grid(TT / BM, nbh);   // 512 CTAs
    dim3 block(NTHREADS);
    fattn_v13<<<grid, block, SMEM_BYTES>>>(out);
}

// round 15
// speedup vs baseline: 1.1509x; 1.1509x over previous
#include <cuda_runtime.h>
#include <cuda_fp16.h>
#include <cstdint>
#include <math.h>

// QKVAttention v14: v12 (2 CTAs/SM, 251 regs) with the mainloop software-
// pipelined: GEMM1 for BOTH n32 chunks is issued before any exp, so ptxas can
// overlap exp(nc0) MUFUs with GEMM1(nc1) MMAs and exp(nc1) with GEMM2(nc0).
// All-fp16 operands (fp32 accum), fragment-order prepacked K/V (1 LDS.128 per
// B-fragment), register-resident P, double-buffered cp.async, 2 barriers/tile.

#define CH 64
#define TT 2048
#define SSEQ 2048
#define BM 128
#define BN 64
#define NTILES (SSEQ / BN)
#define NTHREADS 128
#define MAXELEM (4 * 512 * 2048)

#define PADQ 136    // uint32 units, Q staging 32 rows
#define PADO 132

// fragment-order buffers: K tile = 2048 words (16 blocks x 128), V same
#define KBUF 2048
#define OFF_V (2 * KBUF)     // 4096
#define VBUF 2048
#define SMEM_WORDS 8448      // max(buffers 8192, Osm 64*132=8448)
#define SMEM_BYTES (SMEM_WORDS * 4)

__device__ uint32_t g_Qp[MAXELEM / 2];   // [bh][32 cp][2048 t] fp16x2
__device__ uint32_t g_Kp[MAXELEM / 2];   // [bh][32 tiles][16 blk][32 lane][4 w]
__device__ uint32_t g_Vp[MAXELEM / 2];   // [bh][32 tiles][16 blk][32 lane][4 w]

__device__ __forceinline__ uint32_t smem_u32(const void* p) {
    uint32_t a;
    asm("{ .reg .u64 t; cvta.to.shared.u64 t, %1; cvt.u32.u64 %0, t; }" : "=r"(a) : "l"(p));
    return a;
}
__device__ __forceinline__ void cpa16(uint32_t dst, const void* src) {
    asm volatile("cp.async.cg.shared.global [%0], [%1], 16;" :: "r"(dst), "l"(src));
}
#define CP_COMMIT() asm volatile("cp.async.commit_group;" ::: "memory")
#define CP_WAIT0()  asm volatile("cp.async.wait_group 0;" ::: "memory")
#define CP_WAIT1()  asm volatile("cp.async.wait_group 1;" ::: "memory")

__device__ __forceinline__ uint32_t packh2(float lo, float hi) {
    __half2 h = __floats2half2_rn(lo, hi);
    return *reinterpret_cast<uint32_t*>(&h);
}

__device__ __forceinline__ void mma_f16(float* d, const uint32_t* a, uint32_t b0, uint32_t b1) {
    asm volatile(
        "mma.sync.aligned.m16n8k16.row.col.f32.f16.f16.f32 "
        "{%0,%1,%2,%3}, {%4,%5,%6,%7}, {%8,%9}, {%0,%1,%2,%3};"
        : "+f"(d[0]), "+f"(d[1]), "+f"(d[2]), "+f"(d[3])
        : "r"(a[0]), "r"(a[1]), "r"(a[2]), "r"(a[3]), "r"(b0), "r"(b1));
}

// ---- pre-pass: Q -> fp16x2 [bh][cp][t] (scaled); K,V -> fragment-order ----
__global__ void __launch_bounds__(256)
prep_kernel(const float* __restrict__ q, const float* __restrict__ k,
            const float* __restrict__ v, int nelem) {
    const float qsc = 1.4426950408889634f / 64.0f;  // log2e * (1/64)
    int i = blockIdx.x * blockDim.x + threadIdx.x;
    int ob = i * 4;                       // uint32 output index (16B aligned)
    if (ob >= nelem / 2) return;

    // --- Q: pack channel pairs, [bh][cp][t] ---
    {
        int t4 = ob & (TT - 1);
        int cp = (ob >> 11) & 31;
        int bh = ob >> 16;
        const float* q0 = q + ((size_t)(bh * 64 + 2 * cp)) * TT + t4;
        const float* q1 = q0 + TT;
        float4 qa = *(const float4*)q0;
        float4 qb = *(const float4*)q1;
        uint32_t* oq = g_Qp + ob;
        oq[0] = packh2(qa.x * qsc, qb.x * qsc);
        oq[1] = packh2(qa.y * qsc, qb.y * qsc);
        oq[2] = packh2(qa.z * qsc, qb.z * qsc);
        oq[3] = packh2(qa.w * qsc, qb.w * qsc);
    }

    // shared decomposition for fragment-order outputs
    int lane = (ob >> 2) & 31;
    int blk  = (ob >> 7) & 15;
    int tau  = (ob >> 11) & 31;
    int bh   = ob >> 16;
    int tg = lane & 3, g = lane >> 2;

    // --- K fragment-order: blk = nc*8 + kk*2 + nbh ---
    {
        int nbh = blk & 1, kk = (blk >> 1) & 3, nc = blk >> 3;
        uint32_t* ok = g_Kp + ob;
        #pragma unroll
        for (int w = 0; w < 4; w++) {
            int cp = kk * 8 + tg + (w & 1) * 4;
            int s = tau * 64 + nc * 32 + nbh * 16 + (w >> 1) * 8 + g;
            const float* ksrc = k + ((size_t)(bh * 64 + 2 * cp)) * SSEQ + s;
            ok[w] = packh2(ksrc[0], ksrc[SSEQ]);
        }
    }

    // --- V fragment-order: blk = nc*8 + nb ---
    {
        int nb = blk & 7, nc = blk >> 3;
        int c = nb * 8 + g;
        uint32_t* ov = g_Vp + ob;
        #pragma unroll
        for (int w = 0; w < 4; w++) {
            int sp = tau * 32 + nc * 16 + (w >> 1) * 8 + (w & 1) * 4 + tg;
            const float* vsrc = v + ((size_t)(bh * 64 + c)) * SSEQ + 2 * sp;
            ov[w] = packh2(vsrc[0], vsrc[1]);
        }
    }
}

__global__ void __launch_bounds__(NTHREADS, 2)
fattn_v14(float* __restrict__ out) {
    extern __shared__ float sm[];
    const uint32_t smu = smem_u32(sm);
    uint32_t* smw = reinterpret_cast<uint32_t*>(sm);

    const int tid  = threadIdx.x;
    const int lane = tid & 31;
    const int g    = lane >> 2;
    const int tg   = lane & 3;
    const int bh   = blockIdx.y;
    const int t0   = blockIdx.x * BM;
    const int mw   = (tid >> 5) * 32;    // warp's 32-row slab

    const uint32_t* qp = g_Qp + (size_t)bh * 32 * TT;
    const uint32_t* kp = g_Kp + (size_t)bh * 32 * TT;   // 32 tiles x 2048 words
    const uint32_t* vp = g_Vp + (size_t)bh * 32 * TT;

    // ---- stage packed Q [cp][t], extract fp16 A-frags ----
    #pragma unroll
    for (int j = 0; j < 8; j++) {
        int idx = tid + j * NTHREADS;            // 1024 chunks = 32 rows x 32
        int cp = idx >> 5, t4 = (idx & 31) << 2;
        uint4 r = *(const uint4*)(qp + (size_t)cp * TT + t0 + t4);
        *(uint4*)(smw + cp * PADQ + t4) = r;
    }
    __syncthreads();

    uint32_t Aq[2][4][4];
    #pragma unroll
    for (int mb = 0; mb < 2; mb++) {
        int r = mw + mb * 16;
        #pragma unroll
        for (int kk = 0; kk < 4; kk++) {
            Aq[mb][kk][0] = smw[(kk * 8 + tg)     * PADQ + r + g];
            Aq[mb][kk][1] = smw[(kk * 8 + tg)     * PADQ + r + g + 8];
            Aq[mb][kk][2] = smw[(kk * 8 + tg + 4) * PADQ + r + g];
            Aq[mb][kk][3] = smw[(kk * 8 + tg + 4) * PADQ + r + g + 8];
        }
    }
    __syncthreads();   // Q staging dead; K/V buffers may now be written

    float O[2][8][4];
    #pragma unroll
    for (int mb = 0; mb < 2; mb++)
        #pragma unroll
        for (int nb = 0; nb < 8; nb++)
            O[mb][nb][0] = O[mb][nb][1] = O[mb][nb][2] = O[mb][nb][3] = 0.f;
    float srow[2][2] = {{0.f, 0.f}, {0.f, 0.f}};

    // ---- prologue: async-load tile 0 (linear 16B chunks) ----
    {
        #pragma unroll
        for (int j = 0; j < 4; j++) {
            int idx = tid + j * NTHREADS;        // 512 chunks each
            cpa16(smu + (uint32_t)(idx * 16), kp + idx * 4);
            cpa16(smu + (uint32_t)((OFF_V + idx * 4) * 4), vp + idx * 4);
        }
        CP_COMMIT();
    }

    #pragma unroll 1
    for (int tile = 0; tile < NTILES; tile++) {
        const int nbuf = tile & 1;
        if (tile + 1 < NTILES) {
            const int obuf = (tile + 1) & 1;
            const uint32_t* kt = kp + (size_t)(tile + 1) * 2048;
            const uint32_t* vt = vp + (size_t)(tile + 1) * 2048;
            #pragma unroll
            for (int j = 0; j < 4; j++) {
                int idx = tid + j * NTHREADS;
                cpa16(smu + (uint32_t)((obuf * KBUF + idx * 4) * 4), kt + idx * 4);
                cpa16(smu + (uint32_t)((OFF_V + obuf * VBUF + idx * 4) * 4), vt + idx * 4);
            }
            CP_COMMIT();
            CP_WAIT1();
        } else {
            CP_WAIT0();
        }
        __syncthreads();   // tile's K/V visible; prev readers done (end barrier)

        const uint32_t* Ks = smw + nbuf * KBUF;
        const uint32_t* Vs = smw + OFF_V + nbuf * VBUF;

        // ---- GEMM1 for BOTH n32 chunks first (64 S regs live) ----
        float S[2][4][2][4];
        #pragma unroll
        for (int nc = 0; nc < 2; nc++)
            #pragma unroll
            for (int nbi = 0; nbi < 4; nbi++)
                #pragma unroll
                for (int mb = 0; mb < 2; mb++)
                    S[nc][nbi][mb][0] = S[nc][nbi][mb][1] =
                    S[nc][nbi][mb][2] = S[nc][nbi][mb][3] = 0.f;

        #pragma unroll
        for (int nc = 0; nc < 2; nc++) {
            #pragma unroll
            for (int kk = 0; kk < 4; kk++) {
                #pragma unroll
                for (int nbh = 0; nbh < 2; nbh++) {
                    uint4 F = *(const uint4*)(Ks + nc * 1024 + (kk * 2 + nbh) * 128 + lane * 4);
                    mma_f16(S[nc][2 * nbh + 0][0], Aq[0][kk], F.x, F.y);
                    mma_f16(S[nc][2 * nbh + 0][1], Aq[1][kk], F.x, F.y);
                    mma_f16(S[nc][2 * nbh + 1][0], Aq[0][kk], F.z, F.w);
                    mma_f16(S[nc][2 * nbh + 1][1], Aq[1][kk], F.z, F.w);
                }
            }
        }

        // ---- per chunk: exp2 -> pack fp16 -> GEMM2 partial ----
        // (exp of nc overlaps GEMM2 of nc-1 / GEMM1 tail in ptxas scheduling)
        #pragma unroll
        for (int nc = 0; nc < 2; nc++) {
            uint32_t Ap[2][2][4];   // [j][mb][4]
            #pragma unroll
            for (int j = 0; j < 2; j++) {
                #pragma unroll
                for (int mb = 0; mb < 2; mb++) {
                    float e0 = exp2f(S[nc][2 * j][mb][0]),     e1 = exp2f(S[nc][2 * j][mb][1]);
                    float e2 = exp2f(S[nc][2 * j][mb][2]),     e3 = exp2f(S[nc][2 * j][mb][3]);
                    float f0 = exp2f(S[nc][2 * j + 1][mb][0]), f1 = exp2f(S[nc][2 * j + 1][mb][1]);
                    float f2 = exp2f(S[nc][2 * j + 1][mb][2]), f3 = exp2f(S[nc][2 * j + 1][mb][3]);
                    srow[mb][0] += (e0 + e1) + (f0 + f1);
                    srow[mb][1] += (e2 + e3) + (f2 + f3);
                    Ap[j][mb][0] = packh2(e0, e1);
                    Ap[j][mb][1] = packh2(e2, e3);
                    Ap[j][mb][2] = packh2(f0, f1);
                    Ap[j][mb][3] = packh2(f2, f3);
                }
            }

            #pragma unroll
            for (int nb = 0; nb < 8; nb++) {
                uint4 F = *(const uint4*)(Vs + nc * 1024 + nb * 128 + lane * 4);
                mma_f16(O[0][nb], Ap[0][0], F.x, F.y);
                mma_f16(O[1][nb], Ap[0][1], F.x, F.y);
                mma_f16(O[0][nb], Ap[1][0], F.z, F.w);
                mma_f16(O[1][nb], Ap[1][1], F.z, F.w);
            }
        }
        __syncthreads();   // all warps done reading Ks/Vs before next prefetch
    }

    // ---- row-sum reduce over tg ----
    #pragma unroll
    for (int mb = 0; mb < 2; mb++)
        #pragma unroll
        for (int rr = 0; rr < 2; rr++) {
            float s = srow[mb][rr];
            s += __shfl_xor_sync(0xffffffffu, s, 1);
            s += __shfl_xor_sync(0xffffffffu, s, 2);
            srow[mb][rr] = s;
        }

    // ---- epilogue: normalize + transpose via smem (overlay), coalesced store ----
    float* Osm = sm;
    #pragma unroll
    for (int mb = 0; mb < 2; mb++) {
        float i0 = 1.0f / srow[mb][0];
        float i1 = 1.0f / srow[mb][1];
        int r = mw + mb * 16;
        #pragma unroll
        for (int nb = 0; nb < 8; nb++) {
            int col = nb * 8 + 2 * tg;
            Osm[(col + 0) * PADO + r + g]     = O[mb][nb][0] * i0;
            Osm[(col + 1) * PADO + r + g]     = O[mb][nb][1] * i0;
            Osm[(col + 0) * PADO + r + g + 8] = O[mb][nb][2] * i1;
            Osm[(col + 1) * PADO + r + g + 8] = O[mb][nb][3] * i1;
        }
    }
    __syncthreads();

    float* ob = out + (size_t)bh * CH * TT + t0;
    #pragma unroll
    for (int j = 0; j < 16; j++) {
        int idx = tid + j * NTHREADS;
        int c = idx >> 5, t4 = (idx & 31) << 2;
        *(float4*)(ob + (size_t)c * TT + t4) = *(const float4*)(Osm + c * PADO + t4);
    }
}

extern "C" void kernel_launch(void* const* d_in, const int* in_sizes, int n_in,
                              void* d_out, int out_size) {
    const float* q = (const float*)d_in[0];
    const float* k = (const float*)d_in[1];
    const float* v = (const float*)d_in[2];
    float* out = (float*)d_out;

    int nelem = in_sizes[0];
    int nbh = nelem / (CH * TT);   // 32

    prep_kernel<<<(nelem / 8 + 255) / 256, 256>>>(q, k, v, nelem);

    cudaFuncSetAttribute(fattn_v14,
                         cudaFuncAttributeMaxDynamicSharedMemorySize, SMEM_BYTES);
    dim3 grid(TT / BM, nbh);   // 512 CTAs
    dim3 block(NTHREADS);
    fattn_v14<<<grid, block, SMEM_BYTES>>>(out);
}